// round 1
// baseline (speedup 1.0000x reference)
#include <cuda_runtime.h>

// RNN: h_t = tanh(x_t @ W_ih^T + b_ih + b_hh + h_{t-1} @ W_hh^T), out = h_T @ W_out^T + b_out
// Shapes: x[4096,512,28] f32, W_ih[64,28], W_hh[64,64], b_ih[64], b_hh[64], W_out[10,64], b_out[10]
// Out: [4096, 10] f32

#define BATCH   4096
#define TSTEPS  512
#define IN_DIM  28
#define HID     64
#define OUT_DIM 10
#define BTILE   32
#define NTHREADS 128

__device__ __forceinline__ float fast_tanh(float v) {
    // tanh(v) = 1 - 2/(exp(2v)+1). __expf -> MUFU.EX2; __fdividef -> MUFU.RCP+mul.
    // |error| ~1e-6; handles +/-inf saturation correctly (exp->inf => 0 => 1; exp->0 => -1).
    float e = __expf(2.0f * v);
    return 1.0f - __fdividef(2.0f, e + 1.0f);
}

__global__ void __launch_bounds__(NTHREADS)
rnn_fwd_kernel(const float* __restrict__ x,
               const float* __restrict__ W_ih,
               const float* __restrict__ W_hh,
               const float* __restrict__ b_ih,
               const float* __restrict__ b_hh,
               const float* __restrict__ W_out,
               const float* __restrict__ b_out,
               float* __restrict__ out)
{
    __shared__ float Wt_hh[HID][HID];    // [k][j] = W_hh[j][k]
    __shared__ float Wt_ih[IN_DIM][HID]; // [i][j] = W_ih[j][i]
    __shared__ float h_sh[BTILE][HID];   // [row][k]
    __shared__ float xs[BTILE][IN_DIM];  // [row][i]
    __shared__ float bias[HID];

    const int tid = threadIdx.x;
    const int b0  = blockIdx.x * BTILE;

    // ---- One-time weight staging (transposed so j is contiguous) ----
    for (int idx = tid; idx < HID * HID; idx += NTHREADS) {
        int j = idx / HID, k = idx % HID;   // coalesced read of W_hh
        Wt_hh[k][j] = W_hh[idx];
    }
    for (int idx = tid; idx < IN_DIM * HID; idx += NTHREADS) {
        int j = idx / IN_DIM, i = idx % IN_DIM;
        Wt_ih[i][j] = W_ih[idx];
    }
    if (tid < HID) bias[tid] = b_ih[tid] + b_hh[tid];
    for (int idx = tid; idx < BTILE * HID; idx += NTHREADS)
        (&h_sh[0][0])[idx] = 0.0f;

    // ---- x staging map: thread -> (row = tid>>2, quarter q = tid&3, 7 floats) ----
    const int xrow = tid >> 2;
    const int xq   = tid & 3;
    const float* xbase = x + ((long)(b0 + xrow) * TSTEPS) * IN_DIM + xq * 7;

    float xr[7];
#pragma unroll
    for (int u = 0; u < 7; u++) xr[u] = xbase[u];   // t = 0
#pragma unroll
    for (int u = 0; u < 7; u++) xs[xrow][xq * 7 + u] = xr[u];
    __syncthreads();

    // ---- Compute tile map: 2 rows x 8 cols per thread ----
    const int jb = (tid & 7) * 8;      // column base (0..56)
    const int r0 = tid >> 3;           // 0..15
    const int r1 = r0 + 16;

    float bj[8];
#pragma unroll
    for (int jj = 0; jj < 8; jj++) bj[jj] = bias[jb + jj];

    for (int t = 0; t < TSTEPS; t++) {
        // Prefetch x for t+1 (global latency hidden under the GEMM below)
        if (t + 1 < TSTEPS) {
            const float* xp = xbase + (long)(t + 1) * IN_DIM;
#pragma unroll
            for (int u = 0; u < 7; u++) xr[u] = xp[u];
        }

        float acc0[8], acc1[8];
#pragma unroll
        for (int jj = 0; jj < 8; jj++) { acc0[jj] = bj[jj]; acc1[jj] = bj[jj]; }

        // Input contribution: acc += x[r][i] * W_ih[j][i]
#pragma unroll 4
        for (int i = 0; i < IN_DIM; i++) {
            float x0 = xs[r0][i];
            float x1 = xs[r1][i];
            float4 wa = *(const float4*)&Wt_ih[i][jb];
            float4 wb = *(const float4*)&Wt_ih[i][jb + 4];
            acc0[0] += x0 * wa.x; acc0[1] += x0 * wa.y;
            acc0[2] += x0 * wa.z; acc0[3] += x0 * wa.w;
            acc0[4] += x0 * wb.x; acc0[5] += x0 * wb.y;
            acc0[6] += x0 * wb.z; acc0[7] += x0 * wb.w;
            acc1[0] += x1 * wa.x; acc1[1] += x1 * wa.y;
            acc1[2] += x1 * wa.z; acc1[3] += x1 * wa.w;
            acc1[4] += x1 * wb.x; acc1[5] += x1 * wb.y;
            acc1[6] += x1 * wb.z; acc1[7] += x1 * wb.w;
        }

        // Recurrence: acc += h[r][k] * W_hh[j][k]
#pragma unroll 8
        for (int k = 0; k < HID; k++) {
            float h0 = h_sh[r0][k];
            float h1 = h_sh[r1][k];
            float4 wa = *(const float4*)&Wt_hh[k][jb];
            float4 wb = *(const float4*)&Wt_hh[k][jb + 4];
            acc0[0] += h0 * wa.x; acc0[1] += h0 * wa.y;
            acc0[2] += h0 * wa.z; acc0[3] += h0 * wa.w;
            acc0[4] += h0 * wb.x; acc0[5] += h0 * wb.y;
            acc0[6] += h0 * wb.z; acc0[7] += h0 * wb.w;
            acc1[0] += h1 * wa.x; acc1[1] += h1 * wa.y;
            acc1[2] += h1 * wa.z; acc1[3] += h1 * wa.w;
            acc1[4] += h1 * wb.x; acc1[5] += h1 * wb.y;
            acc1[6] += h1 * wb.z; acc1[7] += h1 * wb.w;
        }

        __syncthreads();   // all reads of h_sh / xs done

        // tanh + writeback (vectorized STS)
        float v0[8], v1[8];
#pragma unroll
        for (int jj = 0; jj < 8; jj++) { v0[jj] = fast_tanh(acc0[jj]); v1[jj] = fast_tanh(acc1[jj]); }
        *(float4*)&h_sh[r0][jb]     = make_float4(v0[0], v0[1], v0[2], v0[3]);
        *(float4*)&h_sh[r0][jb + 4] = make_float4(v0[4], v0[5], v0[6], v0[7]);
        *(float4*)&h_sh[r1][jb]     = make_float4(v1[0], v1[1], v1[2], v1[3]);
        *(float4*)&h_sh[r1][jb + 4] = make_float4(v1[4], v1[5], v1[6], v1[7]);

        if (t + 1 < TSTEPS) {
#pragma unroll
            for (int u = 0; u < 7; u++) xs[xrow][xq * 7 + u] = xr[u];
        }
        __syncthreads();   // new h / x visible
    }

    // ---- Output projection: out[b][o] = h_T[b] . W_out[o] + b_out[o] ----
    for (int idx = tid; idx < BTILE * OUT_DIM; idx += NTHREADS) {
        int r = idx / OUT_DIM;
        int o = idx % OUT_DIM;
        float s = b_out[o];
        const float* wo = W_out + o * HID;
#pragma unroll 16
        for (int j = 0; j < HID; j++) s += h_sh[r][j] * wo[j];
        out[(long)(b0 + r) * OUT_DIM + o] = s;
    }
}

extern "C" void kernel_launch(void* const* d_in, const int* in_sizes, int n_in,
                              void* d_out, int out_size)
{
    const float* x     = (const float*)d_in[0];
    const float* W_ih  = (const float*)d_in[1];
    const float* W_hh  = (const float*)d_in[2];
    const float* b_ih  = (const float*)d_in[3];
    const float* b_hh  = (const float*)d_in[4];
    const float* W_out = (const float*)d_in[5];
    const float* b_out = (const float*)d_in[6];
    float* out = (float*)d_out;

    dim3 grid(BATCH / BTILE);   // 128 CTAs, 32 batch rows each
    dim3 block(NTHREADS);
    rnn_fwd_kernel<<<grid, block>>>(x, W_ih, W_hh, b_ih, b_hh, W_out, b_out, out);
}

// round 2
// speedup vs baseline: 3.6956x; 3.6956x over previous
#include <cuda_runtime.h>
#include <cstdint>

// RNN: h_t = tanh([h_{t-1} | x_t] @ [W_hh | W_ih]^T + b), out = h_T @ W_out^T + b_out
// x[4096,512,28] f32, W_ih[64,28], W_hh[64,64], b_ih[64], b_hh[64], W_out[10,64], b_out[10]
// Strategy: per-CTA persistent 32-row state, tf32 mma.sync m16n8k8 with 3xTF32 split
// (W in registers as A operand, [h|x] streamed from SMEM as B fragments).

#define BATCH    4096
#define TSTEPS   512
#define IN_DIM   28
#define HID      64
#define OUT_DIM  10
#define KCOMB    96          // 64 (h) + 28 (x) + 4 zero pad
#define NCHUNK   12          // KCOMB / 8
#define BTILE    32          // batch rows per CTA
#define NTHREADS 512         // 16 warps: 4 m-groups x 4 n-groups
#define STRIDE   100         // floats per row in B buffer: (n*100+k)%32 = (4n+k)%32 bijective
#define PLANE    (BTILE * STRIDE)   // 3200 floats (one hi or lo plane)
#define BUFSZ    (2 * PLANE)        // hi + lo = 6400 floats (one time-buffer)
#define BIAS_OFF (2 * BUFSZ)        // 12800
#define SMEM_FLOATS (BIAS_OFF + HID)
#define SMEM_BYTES  (SMEM_FLOATS * 4)   // 51456 B

__device__ __forceinline__ uint32_t f2tf(float v) {
    uint32_t r;
    asm("cvt.rna.tf32.f32 %0, %1;" : "=r"(r) : "f"(v));
    return r;
}

__device__ __forceinline__ float fast_tanh(float v) {
    float e = __expf(2.0f * v);
    return 1.0f - __fdividef(2.0f, e + 1.0f);
}

__device__ __forceinline__ void mma8(float* d, const uint32_t* a, const uint32_t* b) {
    asm volatile(
        "mma.sync.aligned.m16n8k8.row.col.f32.tf32.tf32.f32 "
        "{%0,%1,%2,%3}, {%4,%5,%6,%7}, {%8,%9}, {%0,%1,%2,%3};"
        : "+f"(d[0]), "+f"(d[1]), "+f"(d[2]), "+f"(d[3])
        : "r"(a[0]), "r"(a[1]), "r"(a[2]), "r"(a[3]), "r"(b[0]), "r"(b[1]));
}

__global__ void __launch_bounds__(NTHREADS, 1)
rnn_mma_kernel(const float* __restrict__ x,
               const float* __restrict__ W_ih,
               const float* __restrict__ W_hh,
               const float* __restrict__ b_ih,
               const float* __restrict__ b_hh,
               const float* __restrict__ W_out,
               const float* __restrict__ b_out,
               float* __restrict__ out)
{
    extern __shared__ float sm[];
    const int tid  = threadIdx.x;
    const int b0   = blockIdx.x * BTILE;
    const int w    = tid >> 5;
    const int lane = tid & 31;
    const int mg   = w & 3;        // m-group: W columns [mg*16, mg*16+16)
    const int ng   = w >> 2;       // n-group: batch rows [ng*8, ng*8+8)
    const int gid  = lane >> 2;    // 0..7
    const int tig  = lane & 3;     // 0..3

    // ---- Stage combined weight Wc[64][96] (fp32) at sm[0..6144) + bias ----
    for (int idx = tid; idx < HID * KCOMB; idx += NTHREADS) {
        int j = idx / KCOMB, k = idx % KCOMB;
        float v = 0.0f;
        if (k < HID)               v = W_hh[j * HID + k];
        else if (k < HID + IN_DIM) v = W_ih[j * IN_DIM + (k - HID)];
        sm[idx] = v;
    }
    if (tid < HID) sm[BIAS_OFF + tid] = b_ih[tid] + b_hh[tid];
    __syncthreads();

    // ---- Load W fragments into registers (A operand, m16k8 per chunk), split hi/lo ----
    // a0:(gid,tig) a1:(gid+8,tig) a2:(gid,tig+4) a3:(gid+8,tig+4), rows offset mg*16, cols offset c*8
    uint32_t whi[NCHUNK][4], wlo[NCHUNK][4];
#pragma unroll
    for (int c = 0; c < NCHUNK; c++) {
#pragma unroll
        for (int r = 0; r < 4; r++) {
            int j = mg * 16 + gid + (r & 1) * 8;
            int k = c * 8 + tig + (r >> 1) * 4;
            float v = sm[j * KCOMB + k];
            uint32_t hi = f2tf(v);
            whi[c][r] = hi;
            wlo[c][r] = f2tf(v - __uint_as_float(hi));
        }
    }
    const float biasA = sm[BIAS_OFF + mg * 16 + gid];
    const float biasB = sm[BIAS_OFF + mg * 16 + gid + 8];
    __syncthreads();

    // ---- Zero both double-buffers (h = 0, pad region stays 0 forever) ----
    for (int idx = tid; idx < 2 * BUFSZ; idx += NTHREADS) sm[idx] = 0.0f;

    // ---- x loader mapping: 448 threads, each 2 floats (float2) of one row ----
    const int xn_raw = tid / 14;
    const int xn = (xn_raw < BTILE) ? xn_raw : (BTILE - 1);
    const int xp = tid % 14;                       // float2 index within 28-float row
    const float* xptr = x + ((size_t)(b0 + xn) * TSTEPS) * IN_DIM + 2 * xp;

    float2 xr = make_float2(0.0f, 0.0f);
    if (tid < 448) xr = *(const float2*)xptr;       // t = 0
    __syncthreads();                                // zeroing complete

    // store x(t) from xr into buffer p (tf32 hi/lo split)
    auto store_x = [&](int p) {
        if (tid < 448) {
            float* base = sm + p * BUFSZ;
            int k = HID + 2 * xp;
            uint32_t h0 = f2tf(xr.x), h1 = f2tf(xr.y);
            base[xn * STRIDE + k    ] = __uint_as_float(h0);
            base[xn * STRIDE + k + 1] = __uint_as_float(h1);
            base[PLANE + xn * STRIDE + k    ] = __uint_as_float(f2tf(xr.x - __uint_as_float(h0)));
            base[PLANE + xn * STRIDE + k + 1] = __uint_as_float(f2tf(xr.y - __uint_as_float(h1)));
        }
    };

    store_x(0);
    __syncthreads();

    const int nb = ng * 8;                 // batch-row base for this warp's B frags
    const int jA = mg * 16 + gid;          // output W-column (m dim) for acc0/acc1
    const int jB = jA + 8;                 //                          for acc2/acc3
    const int n0 = nb + tig * 2;           // output batch row for acc0/acc2
    const int n1 = n0 + 1;                 //                      acc1/acc3

    int p = 0;
    for (int t = 0; t < TSTEPS; t++) {
        // Prefetch x(t+1) from global (latency hidden under mma below)
        if (t + 1 < TSTEPS && tid < 448)
            xr = *(const float2*)(xptr + (size_t)(t + 1) * IN_DIM);

        float acc[4] = { biasA, biasA, biasB, biasB };

        // B fragment base: element (k = c*8 + tig (+4), n = nb + gid)
        const float* bhiP = sm + p * BUFSZ + (nb + gid) * STRIDE + tig;
        const float* bloP = bhiP + PLANE;

#pragma unroll
        for (int c = 0; c < NCHUNK; c++) {
            uint32_t bh[2], bl[2];
            bh[0] = __float_as_uint(bhiP[c * 8]);
            bh[1] = __float_as_uint(bhiP[c * 8 + 4]);
            bl[0] = __float_as_uint(bloP[c * 8]);
            bl[1] = __float_as_uint(bloP[c * 8 + 4]);
            mma8(acc, whi[c], bh);   // W_hi * b_hi
            mma8(acc, wlo[c], bh);   // W_lo * b_hi
            mma8(acc, whi[c], bl);   // W_hi * b_lo
        }

        // tanh -> new h, tf32 split, write to other buffer
        float v0 = fast_tanh(acc[0]);
        float v1 = fast_tanh(acc[1]);
        float v2 = fast_tanh(acc[2]);
        float v3 = fast_tanh(acc[3]);

        float* nhi = sm + (1 - p) * BUFSZ;
        float* nlo = nhi + PLANE;
        uint32_t u;
        u = f2tf(v0); nhi[n0 * STRIDE + jA] = __uint_as_float(u);
        nlo[n0 * STRIDE + jA] = __uint_as_float(f2tf(v0 - __uint_as_float(u)));
        u = f2tf(v1); nhi[n1 * STRIDE + jA] = __uint_as_float(u);
        nlo[n1 * STRIDE + jA] = __uint_as_float(f2tf(v1 - __uint_as_float(u)));
        u = f2tf(v2); nhi[n0 * STRIDE + jB] = __uint_as_float(u);
        nlo[n0 * STRIDE + jB] = __uint_as_float(f2tf(v2 - __uint_as_float(u)));
        u = f2tf(v3); nhi[n1 * STRIDE + jB] = __uint_as_float(u);
        nlo[n1 * STRIDE + jB] = __uint_as_float(f2tf(v3 - __uint_as_float(u)));

        if (t + 1 < TSTEPS) store_x(1 - p);
        __syncthreads();
        p ^= 1;
    }

    // ---- Output projection: out[b][o] = h_T . W_out[o] + b_out[o] ----
    const float* hf = sm + p * BUFSZ;    // h = hi + lo (exact to ~2^-25)
    for (int idx = tid; idx < BTILE * OUT_DIM; idx += NTHREADS) {
        int r = idx / OUT_DIM;
        int o = idx % OUT_DIM;
        float s = b_out[o];
        const float* wo = W_out + o * HID;
#pragma unroll 16
        for (int j = 0; j < HID; j++)
            s += (hf[r * STRIDE + j] + hf[PLANE + r * STRIDE + j]) * wo[j];
        out[(size_t)(b0 + r) * OUT_DIM + o] = s;
    }
}

extern "C" void kernel_launch(void* const* d_in, const int* in_sizes, int n_in,
                              void* d_out, int out_size)
{
    const float* x     = (const float*)d_in[0];
    const float* W_ih  = (const float*)d_in[1];
    const float* W_hh  = (const float*)d_in[2];
    const float* b_ih  = (const float*)d_in[3];
    const float* b_hh  = (const float*)d_in[4];
    const float* W_out = (const float*)d_in[5];
    const float* b_out = (const float*)d_in[6];
    float* out = (float*)d_out;

    // Dynamic SMEM > 48KB needs opt-in (idempotent, graph-capture safe: no stream op)
    cudaFuncSetAttribute(rnn_mma_kernel,
                         cudaFuncAttributeMaxDynamicSharedMemorySize, SMEM_BYTES);

    dim3 grid(BATCH / BTILE);    // 128 CTAs, 32 persistent batch rows each
    dim3 block(NTHREADS);        // 16 warps
    rnn_mma_kernel<<<grid, block, SMEM_BYTES>>>(x, W_ih, W_hh, b_ih, b_hh,
                                                W_out, b_out, out);
}